// round 5
// baseline (speedup 1.0000x reference)
#include <cuda_runtime.h>
#include <math.h>

#define NB  8
#define CC  64
#define HH  512
#define WW  257
#define BB  8
#define NN  (HH*WW)      // 131584
#define NG  (NN/4)       // 32896 pixel-groups (float4)
#define GX  ((NG + 255) / 256)   // 129 blocks in x
#define TOTAL_BLOCKS (GX * BB)   // 1032

// Device-global scratch (no cudaMalloc allowed). Zero at module load; the
// fused MLP phase snapshots then resets everything, so each graph replay
// starts from a clean state. g_bands4 is recomputed identically every call.
__device__ float        g_acc[BB][NB][4];  // shifted moments
__device__ float        g_cnt[NB];
__device__ float        g_alpha[BB*NB];
__device__ unsigned int g_ticket;
__device__ uchar4       g_bands4[NG];      // band ids, 4 pixels per entry

#define XSHIFT 0.8f   // x = mean-over-channels log1p(|z|) is ~0.81 +- 0.05

__device__ __forceinline__ float f_sqrt_approx(float x){
    float r; asm("sqrt.approx.f32 %0, %1;" : "=f"(r) : "f"(x)); return r;
}
__device__ __forceinline__ float f_lg2_approx(float x){
    float r; asm("lg2.approx.f32 %0, %1;" : "=f"(r) : "f"(x)); return r;
}

// Exact replication of the reference band assignment (bit-identical fp32 ops).
__device__ __forceinline__ int band_of(int n){
    int iy = n / WW;
    int ix = n - iy * WW;
    float fy = (float)(iy < 256 ? iy : iy - 512) * (1.0f/512.0f);
    float fx = (float)ix * (1.0f/512.0f);
    float r  = __fsqrt_rn(fx*fx + fy*fy);
    float rn = __fdiv_rn(r, 0.70710678118654752440f);
    int band = (rn > 0.125f) + (rn > 0.25f) + (rn > 0.375f) + (rn > 0.5f)
             + (rn > 0.625f) + (rn > 0.75f) + (rn > 0.875f);
    return band;
}

__device__ __forceinline__ float fixf(float x){
    if (isnan(x)) return 0.0f;
    if (isinf(x)) return x > 0.f ? 50.0f : -50.0f;
    return x;
}

// ---------------- k_bands: build the uchar4 band table (recomputed per call)
__global__ void __launch_bounds__(256)
k_bands(){
    int g = blockIdx.x * blockDim.x + threadIdx.x;
    if (g >= NG) return;
    int n0 = g * 4;
    uchar4 v;
    v.x = (unsigned char)band_of(n0 + 0);
    v.y = (unsigned char)band_of(n0 + 1);
    v.z = (unsigned char)band_of(n0 + 2);
    v.w = (unsigned char)band_of(n0 + 3);
    g_bands4[g] = v;
}

// ---------------- k_reduce: streaming moment reduction + fused MLP
__global__ void __launch_bounds__(256)
k_reduce(const float* __restrict__ lre, const float* __restrict__ lim,
         const float* __restrict__ hre, const float* __restrict__ him,
         const float* __restrict__ W1,  const float* __restrict__ b1,
         const float* __restrict__ W2,  const float* __restrict__ b2,
         const float* __restrict__ bias){
    __shared__ float s_acc[NB][4];
    __shared__ float s_cnt[NB];
    __shared__ bool  s_last;
    int t    = threadIdx.x;
    int lane = t & 31;
    if (t < NB*4) ((float*)s_acc)[t] = 0.0f;
    if (t < NB)   s_cnt[t] = 0.0f;
    __syncthreads();

    int b = blockIdx.y;
    int g = blockIdx.x * blockDim.x + t;
    if (g < NG) {
        size_t base = ((size_t)b * CC) * (size_t)NN + (size_t)(g * 4);

        float sl0=0.f, sl1=0.f, sl2=0.f, sl3=0.f;
        float sh0=0.f, sh1=0.f, sh2=0.f, sh3=0.f;

        // 8 groups of 8 channels; within a group accumulate PRODUCT of (1+|z|)
        // per pixel slot, then one lg2 per slot per group (8x fewer MUFU lg2).
        for (int grp = 0; grp < 8; grp++){
            float pl0=1.f, pl1=1.f, pl2=1.f, pl3=1.f;
            float ph0=1.f, ph1=1.f, ph2=1.f, ph3=1.f;
            size_t off = base + (size_t)(grp * 8) * NN;
            #pragma unroll
            for (int cc = 0; cc < 8; cc++){
                float4 ar = __ldcs((const float4*)(lre + off));
                float4 ai = __ldcs((const float4*)(lim + off));
                float4 br = __ldcs((const float4*)(hre + off));
                float4 bi = __ldcs((const float4*)(him + off));
                off += NN;

                pl0 *= 1.0f + f_sqrt_approx(ar.x*ar.x + ai.x*ai.x);
                pl1 *= 1.0f + f_sqrt_approx(ar.y*ar.y + ai.y*ai.y);
                pl2 *= 1.0f + f_sqrt_approx(ar.z*ar.z + ai.z*ai.z);
                pl3 *= 1.0f + f_sqrt_approx(ar.w*ar.w + ai.w*ai.w);

                ph0 *= 1.0f + f_sqrt_approx(br.x*br.x + bi.x*bi.x);
                ph1 *= 1.0f + f_sqrt_approx(br.y*br.y + bi.y*bi.y);
                ph2 *= 1.0f + f_sqrt_approx(br.z*br.z + bi.z*bi.z);
                ph3 *= 1.0f + f_sqrt_approx(br.w*br.w + bi.w*bi.w);
            }
            sl0 += f_lg2_approx(pl0);
            sl1 += f_lg2_approx(pl1);
            sl2 += f_lg2_approx(pl2);
            sl3 += f_lg2_approx(pl3);
            sh0 += f_lg2_approx(ph0);
            sh1 += f_lg2_approx(ph1);
            sh2 += f_lg2_approx(ph2);
            sh3 += f_lg2_approx(ph3);
        }

        const float sc = 0.69314718055994530942f / 64.0f;  // ln2 / C
        float dl0 = sl0*sc - XSHIFT, dl1 = sl1*sc - XSHIFT;
        float dl2 = sl2*sc - XSHIFT, dl3 = sl3*sc - XSHIFT;
        float dh0 = sh0*sc - XSHIFT, dh1 = sh1*sc - XSHIFT;
        float dh2 = sh2*sc - XSHIFT, dh3 = sh3*sc - XSHIFT;

        uchar4 tb = g_bands4[g];
        int b0 = tb.x, b1_ = tb.y, b2_ = tb.z, b3_ = tb.w;
        bool merged = (b0 == b1_) && (b0 == b2_) && (b0 == b3_);

        float s1l = dl0+dl1+dl2+dl3;
        float s2l = dl0*dl0+dl1*dl1+dl2*dl2+dl3*dl3;
        float s1h = dh0+dh1+dh2+dh3;
        float s2h = dh0*dh0+dh1*dh1+dh2*dh2+dh3*dh3;

        const unsigned m = 0xffffffffu;
        int  bref = __shfl_sync(m, b0, 0);
        bool uni  = __all_sync(m, merged && (b0 == bref));

        if (uni){
            #pragma unroll
            for (int o = 16; o > 0; o >>= 1){
                s1l += __shfl_xor_sync(m, s1l, o);
                s2l += __shfl_xor_sync(m, s2l, o);
                s1h += __shfl_xor_sync(m, s1h, o);
                s2h += __shfl_xor_sync(m, s2h, o);
            }
            if (lane == 0){
                atomicAdd(&s_acc[bref][0], s1l);
                atomicAdd(&s_acc[bref][1], s2l);
                atomicAdd(&s_acc[bref][2], s1h);
                atomicAdd(&s_acc[bref][3], s2h);
                if (b == 0) atomicAdd(&s_cnt[bref], 128.0f);
            }
        } else if (merged){
            atomicAdd(&s_acc[b0][0], s1l);
            atomicAdd(&s_acc[b0][1], s2l);
            atomicAdd(&s_acc[b0][2], s1h);
            atomicAdd(&s_acc[b0][3], s2h);
            if (b == 0) atomicAdd(&s_cnt[b0], 4.0f);
        } else {
            int   bd[4] = { b0, b1_, b2_, b3_ };
            float xl[4] = { dl0, dl1, dl2, dl3 };
            float xh[4] = { dh0, dh1, dh2, dh3 };
            #pragma unroll
            for (int k = 0; k < 4; k++){
                atomicAdd(&s_acc[bd[k]][0], xl[k]);
                atomicAdd(&s_acc[bd[k]][1], xl[k]*xl[k]);
                atomicAdd(&s_acc[bd[k]][2], xh[k]);
                atomicAdd(&s_acc[bd[k]][3], xh[k]*xh[k]);
                if (b == 0) atomicAdd(&s_cnt[bd[k]], 1.0f);
            }
        }
    }
    __syncthreads();

    if (t < NB*4){
        int bd = t >> 2, q = t & 3;
        float v = s_acc[bd][q];
        if (v != 0.0f) atomicAdd(&g_acc[b][bd][q], v);
    }
    if (t < NB && b == 0){
        float v = s_cnt[t];
        if (v != 0.0f) atomicAdd(&g_cnt[t], v);
    }

    __threadfence();
    __syncthreads();
    if (t == 0){
        unsigned v = atomicAdd(&g_ticket, 1u);
        s_last = (v == (unsigned)(TOTAL_BLOCKS - 1));
    }
    __syncthreads();
    if (!s_last) return;

    __threadfence();  // acquire: make all blocks' atomics visible

    // Phase A: SNAPSHOT accumulators into registers.
    double cnt = 0.0, s1l = 0.0, s2l = 0.0, s1h = 0.0, s2h = 0.0;
    if (t < BB*NB){
        int bb = t >> 3, j = t & 7;
        cnt = (double)__ldcg(&g_cnt[j]);
        s1l = (double)__ldcg(&g_acc[bb][j][0]);
        s2l = (double)__ldcg(&g_acc[bb][j][1]);
        s1h = (double)__ldcg(&g_acc[bb][j][2]);
        s2h = (double)__ldcg(&g_acc[bb][j][3]);
    }

    // Phase B: barrier so no reset can precede any snapshot read.
    __syncthreads();

    // Phase C: reset scratch for the next graph replay.
    if (t < BB*NB*4) ((float*)g_acc)[t] = 0.0f;
    if (t < NB)      g_cnt[t] = 0.0f;
    if (t == 0)      g_ticket = 0u;

    // Phase D: MLP from registers only.
    if (t < BB*NB){
        int j = t & 7;
        double c1  = cnt < 1.0 ? 1.0 : cnt;
        double dml = s1l / c1, dmh = s1h / c1;
        double ml  = (double)XSHIFT + dml;
        double mh  = (double)XSHIFT + dmh;
        double vl  = s2l / c1 - dml*dml; if (vl < 0.0) vl = 0.0;
        double vh  = s2h / c1 - dmh*dmh; if (vh < 0.0) vh = 0.0;

        float fe0 = fixf((float)ml);
        float fe1 = fixf((float)mh);
        float fe2 = fixf((float)sqrt(vl));
        float fe3 = fixf((float)sqrt(vh));

        float acc = b2[0] + bias[j];
        #pragma unroll
        for (int i = 0; i < 32; i++){
            float a = b1[i];
            a += fe0*W1[i*4+0];
            a += fe1*W1[i*4+1];
            a += fe2*W1[i*4+2];
            a += fe3*W1[i*4+3];
            float gl = 0.5f * a * (1.0f + erff(a * 0.70710678118654752440f));
            acc += gl * W2[i];
        }
        g_alpha[t] = 1.0f / (1.0f + expf(-acc));
    }
}

// ---------------- k_write: table-driven alpha broadcast (half the batches)
__global__ void __launch_bounds__(256)
k_write(float* __restrict__ out, int bOff){
    __shared__ float s_alpha[NB];
    int b = blockIdx.y + bOff;
    if (threadIdx.x < NB) s_alpha[threadIdx.x] = g_alpha[b * NB + threadIdx.x];
    __syncthreads();

    int g = blockIdx.x * blockDim.x + threadIdx.x;
    if (g >= NG) return;
    uchar4 tb = g_bands4[g];
    float4 v;
    v.x = s_alpha[tb.x];
    v.y = s_alpha[tb.y];
    v.z = s_alpha[tb.z];
    v.w = s_alpha[tb.w];
    ((float4*)(out + (size_t)b * NN))[g] = v;
}

extern "C" void kernel_launch(void* const* d_in, const int* in_sizes, int n_in,
                              void* d_out, int out_size){
    const float* lre  = (const float*)d_in[0];
    const float* lim  = (const float*)d_in[1];
    const float* hre  = (const float*)d_in[2];
    const float* him  = (const float*)d_in[3];
    const float* W1   = (const float*)d_in[4];
    const float* b1   = (const float*)d_in[5];
    const float* W2   = (const float*)d_in[6];
    const float* b2   = (const float*)d_in[7];
    const float* bias = (const float*)d_in[8];
    float* out = (float*)d_out;

    // 4 launches per call => ncu (-s 5) profiles launch index 5 = k_reduce.
    k_bands<<<GX, 256>>>();
    dim3 grid(GX, BB);
    k_reduce<<<grid, 256>>>(lre, lim, hre, him, W1, b1, W2, b2, bias);
    dim3 wgrid(GX, 4);
    k_write<<<wgrid, 256>>>(out, 0);
    k_write<<<wgrid, 256>>>(out, 4);
}

// round 6
// speedup vs baseline: 1.0427x; 1.0427x over previous
#include <cuda_runtime.h>
#include <math.h>

#define NB  8
#define CC  64
#define HH  512
#define WW  257
#define BB  8
#define NN  (HH*WW)      // 131584
#define NG  (NN/4)       // 32896 pixel-groups (float4)
#define GX  ((NG + 255) / 256)   // 129 blocks in x
#define TOTAL_BLOCKS (GX * BB)   // 1032

// Device-global scratch (no cudaMalloc allowed). Zero at module load; the
// fused MLP phase snapshots then resets everything, so each graph replay
// starts from a clean state.
__device__ float        g_acc[BB][NB][4];  // shifted moments
__device__ float        g_cnt[NB];
__device__ float        g_alpha[BB*NB];
__device__ unsigned int g_ticket;

#define XSHIFT 0.8f   // x = mean-over-channels log1p(|z|) is ~0.81 +- 0.05

__device__ __forceinline__ float f_sqrt_approx(float x){
    float r; asm("sqrt.approx.f32 %0, %1;" : "=f"(r) : "f"(x)); return r;
}
__device__ __forceinline__ float f_lg2_approx(float x){
    float r; asm("lg2.approx.f32 %0, %1;" : "=f"(r) : "f"(x)); return r;
}

// Exact replication of the reference band assignment (bit-identical fp32 ops).
__device__ __forceinline__ int band_of(int n){
    int iy = n / WW;
    int ix = n - iy * WW;
    float fy = (float)(iy < 256 ? iy : iy - 512) * (1.0f/512.0f);
    float fx = (float)ix * (1.0f/512.0f);
    float r  = __fsqrt_rn(fx*fx + fy*fy);
    float rn = __fdiv_rn(r, 0.70710678118654752440f);
    int band = (rn > 0.125f) + (rn > 0.25f) + (rn > 0.375f) + (rn > 0.5f)
             + (rn > 0.625f) + (rn > 0.75f) + (rn > 0.875f);
    return band;
}

__device__ __forceinline__ float fixf(float x){
    if (isnan(x)) return 0.0f;
    if (isinf(x)) return x > 0.f ? 50.0f : -50.0f;
    return x;
}

// consume one channel's 4 arrays worth of float4 into the products
#define CONSUME(AR,AI,BR,BI)                                        \
    pl0 *= 1.0f + f_sqrt_approx((AR).x*(AR).x + (AI).x*(AI).x);     \
    pl1 *= 1.0f + f_sqrt_approx((AR).y*(AR).y + (AI).y*(AI).y);     \
    pl2 *= 1.0f + f_sqrt_approx((AR).z*(AR).z + (AI).z*(AI).z);     \
    pl3 *= 1.0f + f_sqrt_approx((AR).w*(AR).w + (AI).w*(AI).w);     \
    ph0 *= 1.0f + f_sqrt_approx((BR).x*(BR).x + (BI).x*(BI).x);     \
    ph1 *= 1.0f + f_sqrt_approx((BR).y*(BR).y + (BI).y*(BI).y);     \
    ph2 *= 1.0f + f_sqrt_approx((BR).z*(BR).z + (BI).z*(BI).z);     \
    ph3 *= 1.0f + f_sqrt_approx((BR).w*(BR).w + (BI).w*(BI).w);

__global__ void __launch_bounds__(256)
k_reduce(const float* __restrict__ lre, const float* __restrict__ lim,
         const float* __restrict__ hre, const float* __restrict__ him,
         const float* __restrict__ W1,  const float* __restrict__ b1,
         const float* __restrict__ W2,  const float* __restrict__ b2,
         const float* __restrict__ bias){
    __shared__ float s_acc[NB][4];
    __shared__ float s_cnt[NB];
    __shared__ bool  s_last;
    int t    = threadIdx.x;
    int lane = t & 31;
    if (t < NB*4) ((float*)s_acc)[t] = 0.0f;
    if (t < NB)   s_cnt[t] = 0.0f;
    __syncthreads();

    int b = blockIdx.y;
    int g = blockIdx.x * blockDim.x + t;
    if (g < NG) {
        size_t base = ((size_t)b * CC) * (size_t)NN + (size_t)(g * 4);

        float sl0=0.f, sl1=0.f, sl2=0.f, sl3=0.f;
        float sh0=0.f, sh1=0.f, sh2=0.f, sh3=0.f;

        // 8 groups of 8 channels; per group accumulate PRODUCT of (1+|z|) per
        // pixel slot, then one lg2 per slot per group (8x fewer MUFU lg2).
        // Channel loop is software-pipelined 2-deep: 8 LDG.128 are issued
        // before the previous 8 are consumed, keeping 8-16 loads in flight
        // per warp so the ragged last wave still saturates DRAM.
        for (int grp = 0; grp < 8; grp++){
            float pl0=1.f, pl1=1.f, pl2=1.f, pl3=1.f;
            float ph0=1.f, ph1=1.f, ph2=1.f, ph3=1.f;
            size_t off = base + (size_t)(grp * 8) * NN;

            // prologue: cc = 0,1
            float4 ar0 = __ldcs((const float4*)(lre + off));
            float4 ai0 = __ldcs((const float4*)(lim + off));
            float4 br0 = __ldcs((const float4*)(hre + off));
            float4 bi0 = __ldcs((const float4*)(him + off));
            size_t o1 = off + (size_t)NN;
            float4 ar1 = __ldcs((const float4*)(lre + o1));
            float4 ai1 = __ldcs((const float4*)(lim + o1));
            float4 br1 = __ldcs((const float4*)(hre + o1));
            float4 bi1 = __ldcs((const float4*)(him + o1));

            #pragma unroll
            for (int cc = 0; cc < 8; cc += 2){
                float4 nar0, nai0, nbr0, nbi0, nar1, nai1, nbr1, nbi1;
                if (cc < 6){
                    size_t n0o = off + (size_t)(2) * NN * ((cc >> 1) + 1) - (size_t)NN * (cc);  // == off + 2*NN (relative)
                    // compute next offsets plainly:
                    size_t nx0 = off + (size_t)2 * NN;
                    size_t nx1 = nx0 + (size_t)NN;
                    nar0 = __ldcs((const float4*)(lre + nx0));
                    nai0 = __ldcs((const float4*)(lim + nx0));
                    nbr0 = __ldcs((const float4*)(hre + nx0));
                    nbi0 = __ldcs((const float4*)(him + nx0));
                    nar1 = __ldcs((const float4*)(lre + nx1));
                    nai1 = __ldcs((const float4*)(lim + nx1));
                    nbr1 = __ldcs((const float4*)(hre + nx1));
                    nbi1 = __ldcs((const float4*)(him + nx1));
                    (void)n0o;
                }
                CONSUME(ar0, ai0, br0, bi0)
                CONSUME(ar1, ai1, br1, bi1)
                if (cc < 6){
                    ar0 = nar0; ai0 = nai0; br0 = nbr0; bi0 = nbi0;
                    ar1 = nar1; ai1 = nai1; br1 = nbr1; bi1 = nbi1;
                    off += (size_t)2 * NN;
                }
            }

            sl0 += f_lg2_approx(pl0);
            sl1 += f_lg2_approx(pl1);
            sl2 += f_lg2_approx(pl2);
            sl3 += f_lg2_approx(pl3);
            sh0 += f_lg2_approx(ph0);
            sh1 += f_lg2_approx(ph1);
            sh2 += f_lg2_approx(ph2);
            sh3 += f_lg2_approx(ph3);
        }

        const float sc = 0.69314718055994530942f / 64.0f;  // ln2 / C
        float dl0 = sl0*sc - XSHIFT, dl1 = sl1*sc - XSHIFT;
        float dl2 = sl2*sc - XSHIFT, dl3 = sl3*sc - XSHIFT;
        float dh0 = sh0*sc - XSHIFT, dh1 = sh1*sc - XSHIFT;
        float dh2 = sh2*sc - XSHIFT, dh3 = sh3*sc - XSHIFT;

        int n0 = g * 4;
        int b0 = band_of(n0+0), b1_ = band_of(n0+1), b2_ = band_of(n0+2), b3_ = band_of(n0+3);
        bool merged = (b0 == b1_) && (b0 == b2_) && (b0 == b3_);

        float s1l = dl0+dl1+dl2+dl3;
        float s2l = dl0*dl0+dl1*dl1+dl2*dl2+dl3*dl3;
        float s1h = dh0+dh1+dh2+dh3;
        float s2h = dh0*dh0+dh1*dh1+dh2*dh2+dh3*dh3;

        const unsigned m = 0xffffffffu;
        int  bref = __shfl_sync(m, b0, 0);
        bool uni  = __all_sync(m, merged && (b0 == bref));

        if (uni){
            #pragma unroll
            for (int o = 16; o > 0; o >>= 1){
                s1l += __shfl_xor_sync(m, s1l, o);
                s2l += __shfl_xor_sync(m, s2l, o);
                s1h += __shfl_xor_sync(m, s1h, o);
                s2h += __shfl_xor_sync(m, s2h, o);
            }
            if (lane == 0){
                atomicAdd(&s_acc[bref][0], s1l);
                atomicAdd(&s_acc[bref][1], s2l);
                atomicAdd(&s_acc[bref][2], s1h);
                atomicAdd(&s_acc[bref][3], s2h);
                if (b == 0) atomicAdd(&s_cnt[bref], 128.0f);
            }
        } else if (merged){
            atomicAdd(&s_acc[b0][0], s1l);
            atomicAdd(&s_acc[b0][1], s2l);
            atomicAdd(&s_acc[b0][2], s1h);
            atomicAdd(&s_acc[b0][3], s2h);
            if (b == 0) atomicAdd(&s_cnt[b0], 4.0f);
        } else {
            int   bd[4] = { b0, b1_, b2_, b3_ };
            float xl[4] = { dl0, dl1, dl2, dl3 };
            float xh[4] = { dh0, dh1, dh2, dh3 };
            #pragma unroll
            for (int k = 0; k < 4; k++){
                atomicAdd(&s_acc[bd[k]][0], xl[k]);
                atomicAdd(&s_acc[bd[k]][1], xl[k]*xl[k]);
                atomicAdd(&s_acc[bd[k]][2], xh[k]);
                atomicAdd(&s_acc[bd[k]][3], xh[k]*xh[k]);
                if (b == 0) atomicAdd(&s_cnt[bd[k]], 1.0f);
            }
        }
    }
    __syncthreads();

    if (t < NB*4){
        int bd = t >> 2, q = t & 3;
        float v = s_acc[bd][q];
        if (v != 0.0f) atomicAdd(&g_acc[b][bd][q], v);
    }
    if (t < NB && b == 0){
        float v = s_cnt[t];
        if (v != 0.0f) atomicAdd(&g_cnt[t], v);
    }

    __threadfence();
    __syncthreads();
    if (t == 0){
        unsigned v = atomicAdd(&g_ticket, 1u);
        s_last = (v == (unsigned)(TOTAL_BLOCKS - 1));
    }
    __syncthreads();
    if (!s_last) return;

    __threadfence();  // acquire: make all blocks' atomics visible

    // Phase A: SNAPSHOT accumulators into registers.
    double cnt = 0.0, s1l = 0.0, s2l = 0.0, s1h = 0.0, s2h = 0.0;
    if (t < BB*NB){
        int bb = t >> 3, j = t & 7;
        cnt = (double)__ldcg(&g_cnt[j]);
        s1l = (double)__ldcg(&g_acc[bb][j][0]);
        s2l = (double)__ldcg(&g_acc[bb][j][1]);
        s1h = (double)__ldcg(&g_acc[bb][j][2]);
        s2h = (double)__ldcg(&g_acc[bb][j][3]);
    }

    // Phase B: barrier so no reset can precede any snapshot read.
    __syncthreads();

    // Phase C: reset scratch for the next graph replay.
    if (t < BB*NB*4) ((float*)g_acc)[t] = 0.0f;
    if (t < NB)      g_cnt[t] = 0.0f;
    if (t == 0)      g_ticket = 0u;

    // Phase D: MLP from registers only.
    if (t < BB*NB){
        int j = t & 7;
        double c1  = cnt < 1.0 ? 1.0 : cnt;
        double dml = s1l / c1, dmh = s1h / c1;
        double ml  = (double)XSHIFT + dml;
        double mh  = (double)XSHIFT + dmh;
        double vl  = s2l / c1 - dml*dml; if (vl < 0.0) vl = 0.0;
        double vh  = s2h / c1 - dmh*dmh; if (vh < 0.0) vh = 0.0;

        float fe0 = fixf((float)ml);
        float fe1 = fixf((float)mh);
        float fe2 = fixf((float)sqrt(vl));
        float fe3 = fixf((float)sqrt(vh));

        float acc = b2[0] + bias[j];
        #pragma unroll
        for (int i = 0; i < 32; i++){
            float a = b1[i];
            a += fe0*W1[i*4+0];
            a += fe1*W1[i*4+1];
            a += fe2*W1[i*4+2];
            a += fe3*W1[i*4+3];
            float gl = 0.5f * a * (1.0f + erff(a * 0.70710678118654752440f));
            acc += gl * W2[i];
        }
        g_alpha[t] = 1.0f / (1.0f + expf(-acc));
    }
}

__global__ void __launch_bounds__(256)
k_write(float* __restrict__ out){
    __shared__ float s_alpha[BB*NB];
    if (threadIdx.x < BB*NB) s_alpha[threadIdx.x] = g_alpha[threadIdx.x];
    __syncthreads();

    const int T4 = BB * NG;  // total float4 stores
    int stride = gridDim.x * blockDim.x;
    for (int i = blockIdx.x * blockDim.x + threadIdx.x; i < T4; i += stride){
        int b  = i / NG;
        int g  = i - b * NG;
        int n0 = g * 4;
        const float* ab = &s_alpha[b * NB];
        float4 v;
        v.x = ab[band_of(n0 + 0)];
        v.y = ab[band_of(n0 + 1)];
        v.z = ab[band_of(n0 + 2)];
        v.w = ab[band_of(n0 + 3)];
        *(float4*)(out + (size_t)b * NN + n0) = v;
    }
}

extern "C" void kernel_launch(void* const* d_in, const int* in_sizes, int n_in,
                              void* d_out, int out_size){
    const float* lre  = (const float*)d_in[0];
    const float* lim  = (const float*)d_in[1];
    const float* hre  = (const float*)d_in[2];
    const float* him  = (const float*)d_in[3];
    const float* W1   = (const float*)d_in[4];
    const float* b1   = (const float*)d_in[5];
    const float* W2   = (const float*)d_in[6];
    const float* b2   = (const float*)d_in[7];
    const float* bias = (const float*)d_in[8];
    float* out = (float*)d_out;

    dim3 grid(GX, BB);
    k_reduce<<<grid, 256>>>(lre, lim, hre, him, W1, b1, W2, b2, bias);
    k_write<<<592, 256>>>(out);
}